// round 1
// baseline (speedup 1.0000x reference)
#include <cuda_runtime.h>
#include <cuda_bf16.h>
#include <math.h>

// Problem constants
#define IN_F      4096
#define OUT_F     11008
#define N_CLUST   16
#define TOPK      1024

// Scratch (no allocations allowed in kernel_launch)
__device__ float g_act[IN_F];   // softmax(|x|)
__device__ float g_d2[N_CLUST]; // squared distances
__device__ float g_xm[IN_F];    // masked x (x[i] if column selected else 0)

// ---------------------------------------------------------------------------
// Kernel 1: activation = softmax(|x|), single block, 1024 threads (4 elem/thr)
// ---------------------------------------------------------------------------
__global__ void __launch_bounds__(1024) k_softmax(const float* __restrict__ x) {
    __shared__ float red[32];
    __shared__ float s_b;
    int tid = threadIdx.x;

    float v0 = fabsf(x[tid]);
    float v1 = fabsf(x[tid + 1024]);
    float v2 = fabsf(x[tid + 2048]);
    float v3 = fabsf(x[tid + 3072]);

    // ---- block max ----
    float m = fmaxf(fmaxf(v0, v1), fmaxf(v2, v3));
    #pragma unroll
    for (int o = 16; o > 0; o >>= 1) m = fmaxf(m, __shfl_xor_sync(0xffffffffu, m, o));
    if ((tid & 31) == 0) red[tid >> 5] = m;
    __syncthreads();
    if (tid < 32) {
        float t = red[tid];
        #pragma unroll
        for (int o = 16; o > 0; o >>= 1) t = fmaxf(t, __shfl_xor_sync(0xffffffffu, t, o));
        if (tid == 0) s_b = t;
    }
    __syncthreads();
    float M = s_b;

    float e0 = __expf(v0 - M);
    float e1 = __expf(v1 - M);
    float e2 = __expf(v2 - M);
    float e3 = __expf(v3 - M);

    // ---- block sum ----
    float s = (e0 + e1) + (e2 + e3);
    #pragma unroll
    for (int o = 16; o > 0; o >>= 1) s += __shfl_xor_sync(0xffffffffu, s, o);
    __syncthreads();                 // protect red[] reuse
    if ((tid & 31) == 0) red[tid >> 5] = s;
    __syncthreads();
    if (tid < 32) {
        float t = red[tid];
        #pragma unroll
        for (int o = 16; o > 0; o >>= 1) t += __shfl_xor_sync(0xffffffffu, t, o);
        if (tid == 0) s_b = t;
    }
    __syncthreads();
    float inv = 1.0f / s_b;

    g_act[tid]        = e0 * inv;
    g_act[tid + 1024] = e1 * inv;
    g_act[tid + 2048] = e2 * inv;
    g_act[tid + 3072] = e3 * inv;
}

// ---------------------------------------------------------------------------
// Kernel 2: per-cluster squared L2 distance to activation. 16 blocks x 256 thr
// ---------------------------------------------------------------------------
__global__ void __launch_bounds__(256) k_dist(const float* __restrict__ centers) {
    __shared__ float red[8];
    int k   = blockIdx.x;
    int tid = threadIdx.x;
    const float* c = centers + (size_t)k * IN_F;

    float s = 0.0f;
    #pragma unroll 4
    for (int i = tid; i < IN_F; i += 256) {
        float d = c[i] - g_act[i];
        s += d * d;
    }
    #pragma unroll
    for (int o = 16; o > 0; o >>= 1) s += __shfl_xor_sync(0xffffffffu, s, o);
    if ((tid & 31) == 0) red[tid >> 5] = s;
    __syncthreads();
    if (tid == 0) {
        float t = 0.0f;
        #pragma unroll
        for (int w = 0; w < 8; w++) t += red[w];
        g_d2[k] = t;
    }
}

// ---------------------------------------------------------------------------
// Kernel 3: argmin over clusters; radix-select top-1024 of chosen center;
// write masked x. Single block, 1024 threads.
// Float->uint order is monotonic because centers are softmax outputs (>0).
// ---------------------------------------------------------------------------
__global__ void __launch_bounds__(1024) k_select(const float* __restrict__ x,
                                                 const float* __restrict__ centers) {
    __shared__ unsigned int keys[IN_F];       // 16 KB
    __shared__ unsigned int hist[256];
    __shared__ int s_ci;
    __shared__ unsigned int s_prefix;
    __shared__ int s_k;

    int tid = threadIdx.x;

    if (tid == 0) {
        float best = g_d2[0]; int bi = 0;
        #pragma unroll
        for (int i = 1; i < N_CLUST; i++)
            if (g_d2[i] < best) { best = g_d2[i]; bi = i; }
        s_ci = bi;
        s_prefix = 0u;
        s_k = TOPK;
    }
    __syncthreads();

    const float* c = centers + (size_t)s_ci * IN_F;
    #pragma unroll
    for (int j = 0; j < 4; j++)
        keys[tid + j * 1024] = __float_as_uint(c[tid + j * 1024]);
    __syncthreads();

    // 4 radix rounds, MSB-first, 8-bit digits
    for (int r = 0; r < 4; r++) {
        int shift = 24 - 8 * r;
        if (tid < 256) hist[tid] = 0u;
        __syncthreads();

        unsigned int hi_mask = (r == 0) ? 0u : (0xFFFFFFFFu << (shift + 8));
        unsigned int pref = s_prefix;
        #pragma unroll
        for (int j = 0; j < 4; j++) {
            unsigned int key = keys[tid + j * 1024];
            if (((key ^ pref) & hi_mask) == 0u)
                atomicAdd(&hist[(key >> shift) & 0xFFu], 1u);
        }
        __syncthreads();
        if (tid == 0) {
            int k = s_k;
            unsigned int cum = 0;
            int d = 255;
            for (; d > 0; d--) {
                unsigned int h = hist[d];
                if (cum + h >= (unsigned int)k) break;
                cum += h;
            }
            s_prefix = pref | ((unsigned int)d << shift);
            s_k = k - (int)cum;   // still to take among keys with this digit
        }
        __syncthreads();
    }

    unsigned int thr = s_prefix;  // exact key of the K-th largest
    int rem = s_k;                // how many == thr to include (lowest indices)

    #pragma unroll
    for (int j = 0; j < 4; j++) {
        int i = tid + j * 1024;
        unsigned int key = keys[i];
        bool sel = (key > thr);
        if (!sel && key == thr) {
            // rank among equal keys by index (matches jax.lax.top_k tie order)
            int cnt = 0;
            for (int t = 0; t < i; t++) cnt += (keys[t] == thr);
            sel = (cnt < rem);
        }
        g_xm[i] = sel ? x[i] : 0.0f;
    }
}

// ---------------------------------------------------------------------------
// Kernel 4: dense masked GEMV. out[r] = bias[r] + sum_i xm[i]*W[r][i].
// Warp-per-row, float4 coalesced reads of W. 180 MB -> DRAM-bound.
// ---------------------------------------------------------------------------
__global__ void __launch_bounds__(256) k_gemv(const float* __restrict__ W,
                                              const float* __restrict__ bias,
                                              float* __restrict__ out) {
    __shared__ float4 xs[IN_F / 4];   // 16 KB masked x

    int tid = threadIdx.x;
    const float4* xm4 = (const float4*)g_xm;
    #pragma unroll
    for (int j = tid; j < IN_F / 4; j += 256) xs[j] = xm4[j];
    __syncthreads();

    int warp = tid >> 5;
    int lane = tid & 31;
    int row  = blockIdx.x * 8 + warp;
    if (row >= OUT_F) return;

    const float4* w4 = (const float4*)(W + (size_t)row * IN_F);

    float acc = 0.0f;
    #pragma unroll 8
    for (int i = 0; i < IN_F / 4 / 32; i++) {      // 32 iterations
        float4 w  = w4[i * 32 + lane];
        float4 xv = xs[i * 32 + lane];
        acc += w.x * xv.x + w.y * xv.y + w.z * xv.z + w.w * xv.w;
    }
    #pragma unroll
    for (int o = 16; o > 0; o >>= 1) acc += __shfl_xor_sync(0xffffffffu, acc, o);
    if (lane == 0) out[row] = acc + bias[row];
}

// ---------------------------------------------------------------------------
extern "C" void kernel_launch(void* const* d_in, const int* in_sizes, int n_in,
                              void* d_out, int out_size) {
    const float* x       = (const float*)d_in[0];   // [1,1,4096]
    const float* W       = (const float*)d_in[1];   // [11008,4096]
    const float* bias    = (const float*)d_in[2];   // [11008]
    const float* centers = (const float*)d_in[3];   // [16,4096]
    float* out = (float*)d_out;                     // [1,1,11008]

    k_softmax<<<1, 1024>>>(x);
    k_dist<<<N_CLUST, 256>>>(centers);
    k_select<<<1, 1024>>>(x, centers);
    k_gemv<<<(OUT_F + 7) / 8, 256>>>(W, bias, out);
}

// round 2
// speedup vs baseline: 1.7684x; 1.7684x over previous
#include <cuda_runtime.h>
#include <cuda_bf16.h>
#include <math.h>

#define IN_F      4096
#define OUT_F     11008
#define N_CLUST   16
#define TOPK      1024

// Scratch (no allocations allowed)
__device__ float g_xm[IN_F];    // masked x (x[i] if column selected else 0)

// ===========================================================================
// Fused prep kernel: softmax(|x|) -> nearest center -> radix top-1024 select
// -> write masked x. One block, 1024 threads. All stages parallel (scans, no
// serial loops).
// Float bit-pattern order == float order here: centers are softmax outputs>0.
// ===========================================================================
__global__ void __launch_bounds__(1024) k_prep(const float* __restrict__ x,
                                               const float* __restrict__ centers) {
    __shared__ float        s_act[IN_F];     // 16 KB: softmax activation
    __shared__ float        red[32];
    __shared__ float        s_scalar;
    __shared__ float        s_d2[N_CLUST];
    __shared__ unsigned int hist[256];
    __shared__ unsigned int wsum[32], woff[32];
    __shared__ int          s_ci;
    __shared__ unsigned int s_prefix;
    __shared__ int          s_k;

    const int tid  = threadIdx.x;
    const int lane = tid & 31;
    const int wid  = tid >> 5;

    if (tid < N_CLUST) s_d2[tid] = 0.0f;
    if (tid == 0) { s_prefix = 0u; s_k = TOPK; }

    // ---------------- softmax(|x|) ----------------
    float v0 = fabsf(x[tid]);
    float v1 = fabsf(x[tid + 1024]);
    float v2 = fabsf(x[tid + 2048]);
    float v3 = fabsf(x[tid + 3072]);

    float m = fmaxf(fmaxf(v0, v1), fmaxf(v2, v3));
    #pragma unroll
    for (int o = 16; o > 0; o >>= 1) m = fmaxf(m, __shfl_xor_sync(0xffffffffu, m, o));
    if (lane == 0) red[wid] = m;
    __syncthreads();
    if (tid < 32) {
        float t = red[tid];
        #pragma unroll
        for (int o = 16; o > 0; o >>= 1) t = fmaxf(t, __shfl_xor_sync(0xffffffffu, t, o));
        if (tid == 0) s_scalar = t;
    }
    __syncthreads();
    const float M = s_scalar;

    float e0 = __expf(v0 - M);
    float e1 = __expf(v1 - M);
    float e2 = __expf(v2 - M);
    float e3 = __expf(v3 - M);

    float s = (e0 + e1) + (e2 + e3);
    #pragma unroll
    for (int o = 16; o > 0; o >>= 1) s += __shfl_xor_sync(0xffffffffu, s, o);
    __syncthreads();
    if (lane == 0) red[wid] = s;
    __syncthreads();
    if (tid < 32) {
        float t = red[tid];
        #pragma unroll
        for (int o = 16; o > 0; o >>= 1) t += __shfl_xor_sync(0xffffffffu, t, o);
        if (tid == 0) s_scalar = t;
    }
    __syncthreads();
    const float inv = 1.0f / s_scalar;

    s_act[tid]        = e0 * inv;
    s_act[tid + 1024] = e1 * inv;
    s_act[tid + 2048] = e2 * inv;
    s_act[tid + 3072] = e3 * inv;
    __syncthreads();

    // ---------------- squared distances to 16 centers ----------------
    // 32 warps: cluster = wid & 15, half = wid >> 4. Each lane: 16 float4.
    {
        const int c = wid & 15;
        const int h = wid >> 4;
        const float4* c4 = (const float4*)(centers + (size_t)c * IN_F);
        const float4* a4 = (const float4*)s_act;
        float acc = 0.0f;
        #pragma unroll
        for (int t = 0; t < 16; t++) {
            int i = h * 512 + t * 32 + lane;
            float4 cv = c4[i];
            float4 av = a4[i];
            float dx = cv.x - av.x, dy = cv.y - av.y;
            float dz = cv.z - av.z, dw = cv.w - av.w;
            acc += dx * dx + dy * dy + dz * dz + dw * dw;
        }
        #pragma unroll
        for (int o = 16; o > 0; o >>= 1) acc += __shfl_xor_sync(0xffffffffu, acc, o);
        if (lane == 0) atomicAdd(&s_d2[c], acc);
    }
    __syncthreads();

    // ---------------- argmin (one warp) ----------------
    if (tid < 32) {
        float v = (tid < N_CLUST) ? s_d2[tid] : 3.4e38f;
        int   bi = tid;
        #pragma unroll
        for (int o = 8; o > 0; o >>= 1) {
            float ov = __shfl_down_sync(0xffffffffu, v, o);
            int   oi = __shfl_down_sync(0xffffffffu, bi, o);
            if (ov < v || (ov == v && oi < bi)) { v = ov; bi = oi; }
        }
        if (tid == 0) s_ci = bi;
    }
    __syncthreads();

    // ---------------- load chosen center keys (registers, blocked uint4) ----
    const uint4 kk = ((const uint4*)(centers + (size_t)s_ci * IN_F))[tid];

    // ---------------- radix select: 4 rounds, MSB-first 8-bit digits --------
    #pragma unroll
    for (int r = 0; r < 4; r++) {
        const int shift = 24 - 8 * r;
        if (tid < 256) hist[tid] = 0u;
        __syncthreads();

        const unsigned int pref   = s_prefix;
        const int          kreg   = s_k;
        const unsigned int himask = (r == 0) ? 0u : (0xFFFFFFFFu << (shift + 8));

        if (((kk.x ^ pref) & himask) == 0u) atomicAdd(&hist[(kk.x >> shift) & 255u], 1u);
        if (((kk.y ^ pref) & himask) == 0u) atomicAdd(&hist[(kk.y >> shift) & 255u], 1u);
        if (((kk.z ^ pref) & himask) == 0u) atomicAdd(&hist[(kk.z >> shift) & 255u], 1u);
        if (((kk.w ^ pref) & himask) == 0u) atomicAdd(&hist[(kk.w >> shift) & 255u], 1u);
        __syncthreads();

        // parallel suffix sum over bins (tid<256: bin b = 255-tid)
        unsigned int v = 0u, incl = 0u;
        if (tid < 256) v = hist[255 - tid];
        incl = v;
        #pragma unroll
        for (int o = 1; o < 32; o <<= 1) {
            unsigned int u = __shfl_up_sync(0xffffffffu, incl, o);
            if (lane >= o) incl += u;
        }
        if (tid < 256 && lane == 31) wsum[wid] = incl;
        __syncthreads();
        if (tid == 0) {
            unsigned int run = 0u;
            #pragma unroll
            for (int w = 0; w < 8; w++) { woff[w] = run; run += wsum[w]; }
        }
        __syncthreads();
        if (tid < 256) {
            unsigned int S     = incl + woff[wid];   // suffix-incl at bin b
            unsigned int Sprev = S - v;              // sum over bins > b
            if ((int)S >= kreg && (int)Sprev < kreg) {
                int b = 255 - tid;
                s_prefix = pref | ((unsigned int)b << shift);
                s_k      = kreg - (int)Sprev;
            }
        }
        __syncthreads();
    }

    const unsigned int thr = s_prefix;  // exact key bits of K-th largest
    const int          rem = s_k;       // # of ==thr to include (lowest idx)

    // ---------------- tie rank via block exclusive scan ----------------
    const int c0 = (kk.x == thr), c1 = (kk.y == thr);
    const int c2 = (kk.z == thr), c3 = (kk.w == thr);
    int cnt = c0 + c1 + c2 + c3;
    int inc = cnt;
    #pragma unroll
    for (int o = 1; o < 32; o <<= 1) {
        int u = __shfl_up_sync(0xffffffffu, inc, o);
        if (lane >= o) inc += u;
    }
    if (lane == 31) wsum[wid] = (unsigned int)inc;
    __syncthreads();
    if (tid == 0) {
        unsigned int run = 0u;
        #pragma unroll
        for (int w = 0; w < 32; w++) { woff[w] = run; run += wsum[w]; }
    }
    __syncthreads();
    int excl = inc - cnt + (int)woff[wid];  // ties strictly before this thread

    // ---------------- write masked x ----------------
    const float4 xv = ((const float4*)x)[tid];
    float4 o;
    int q = rem - excl;  // remaining tie quota at this thread's first tie
    o.x = (kk.x > thr || (c0 && q > 0)) ? xv.x : 0.0f;  q -= c0;
    o.y = (kk.y > thr || (c1 && q > 0)) ? xv.y : 0.0f;  q -= c1;
    o.z = (kk.z > thr || (c2 && q > 0)) ? xv.z : 0.0f;  q -= c2;
    o.w = (kk.w > thr || (c3 && q > 0)) ? xv.w : 0.0f;  q -= c3;
    ((float4*)g_xm)[tid] = o;
}

// ===========================================================================
// Dense masked GEMV: out[r] = bias[r] + sum_i xm[i]*W[r][i]. Warp-per-row,
// float4 streaming loads of W (read-once). DRAM-bound.
// ===========================================================================
__global__ void __launch_bounds__(256) k_gemv(const float* __restrict__ W,
                                              const float* __restrict__ bias,
                                              float* __restrict__ out) {
    __shared__ float4 xs[IN_F / 4];   // 16 KB masked x

    const int tid = threadIdx.x;
    const float4* xm4 = (const float4*)g_xm;
    #pragma unroll
    for (int j = tid; j < IN_F / 4; j += 256) xs[j] = xm4[j];
    __syncthreads();

    const int warp = tid >> 5;
    const int lane = tid & 31;
    const int row  = blockIdx.x * 8 + warp;
    if (row >= OUT_F) return;

    const float4* w4 = (const float4*)(W + (size_t)row * IN_F);

    float acc = 0.0f;
    #pragma unroll 8
    for (int i = 0; i < IN_F / 4 / 32; i++) {      // 32 iterations
        float4 w  = __ldcs(&w4[i * 32 + lane]);
        float4 xv = xs[i * 32 + lane];
        acc += w.x * xv.x + w.y * xv.y + w.z * xv.z + w.w * xv.w;
    }
    #pragma unroll
    for (int o = 16; o > 0; o >>= 1) acc += __shfl_xor_sync(0xffffffffu, acc, o);
    if (lane == 0) out[row] = acc + bias[row];
}

// ===========================================================================
extern "C" void kernel_launch(void* const* d_in, const int* in_sizes, int n_in,
                              void* d_out, int out_size) {
    const float* x       = (const float*)d_in[0];   // [1,1,4096]
    const float* W       = (const float*)d_in[1];   // [11008,4096]
    const float* bias    = (const float*)d_in[2];   // [11008]
    const float* centers = (const float*)d_in[3];   // [16,4096]
    float* out = (float*)d_out;                     // [1,1,11008]

    k_prep<<<1, 1024>>>(x, centers);
    k_gemv<<<(OUT_F + 7) / 8, 256>>>(W, bias, out);
}